// round 4
// baseline (speedup 1.0000x reference)
#include <cuda_runtime.h>
#include <cstdint>

// Problem constants
#define B_DIM    512
#define QB       128            // batch rows per quarter
#define IN_DIM   65536
#define OUT_DIM  16384
#define K_DIM    32
#define OTILE    8

// Task accounting
#define TT       2048           // transpose tiles per quarter: (IN/128)*(QB/32)
#define GT       2048           // gather tasks per quarter: OUT/OTILE
#define TOTAL_TASKS 16384       // 4*(TT+GT)

// 128 MB scratch for transposed x: xt[in][b]
__device__ float g_xt[(size_t)IN_DIM * B_DIM];

// Scheduling state (reset every call by reset_kernel)
__device__ int g_task_ctr;
__device__ int g_tdone[4];      // transpose tiles completed per quarter

__global__ void reset_kernel() {
    g_task_ctr = 0;
    g_tdone[0] = 0; g_tdone[1] = 0; g_tdone[2] = 0; g_tdone[3] = 0;
}

// ---------------------------------------------------------------------------
// Persistent worker: claims tasks from a global counter.
//   Task order: [T q0][G q0 + T q1 interleaved][G q1 + T q2][G q2 + T q3][G q3]
//   T task (q, j): transpose a 32b x 128in tile of x into xt.
//   G task (q, i): compute out[b in quarter q][8 outputs], spin until T_q done.
// ---------------------------------------------------------------------------
__global__ __launch_bounds__(256) void persistent_kernel(
    const float* __restrict__ x,
    const int*   __restrict__ idx,
    const float* __restrict__ w,
    const float* __restrict__ bias,
    float*       __restrict__ out)
{
    __shared__ int s_task;
    __shared__ union {
        float4 tile4[32][33];                       // transpose staging (16.9KB)
        struct {
            int4   sidx4[OTILE][K_DIM / 4];
            float4 sw4[OTILE][K_DIM / 4];
            float  sbias[OTILE];
            float  sout2[OTILE][QB + 4];            // [o][b], pad 4
        } g;
    } sm;

    const int tid = threadIdx.x;

    while (true) {
        __syncthreads();                            // protect smem reuse
        if (tid == 0) s_task = atomicAdd(&g_task_ctr, 1);
        __syncthreads();
        const int t = s_task;
        if (t >= TOTAL_TASKS) break;

        // ---- decode task ----
        int q, j, isT;
        if (t < TT) {
            isT = 1; q = 0; j = t;
        } else if (t < TT + 3 * (TT + GT)) {        // < 14336
            const int r   = t - TT;
            const int blk = r >> 12;                // / (TT+GT)=4096
            const int off = r & 4095;
            if (off & 1) { isT = 1; q = blk + 1; j = off >> 1; }
            else         { isT = 0; q = blk;     j = off >> 1; }
        } else {
            isT = 0; q = 3; j = t - (TT + 3 * (TT + GT));
        }

        if (isT) {
            // ================= transpose tile =================
            const int in0 = (j & 511) << 7;          // 0..65408 step 128
            const int b0  = q * QB + (j >> 9) * 32;  // 32-row band

            const int c4 = tid & 31;
            const int r0 = tid >> 5;
            #pragma unroll
            for (int it = 0; it < 4; it++) {
                const int r = r0 + 8 * it;
                sm.tile4[r][c4] =
                    *(const float4*)&x[(size_t)(b0 + r) * IN_DIM + in0 + 4 * c4];
            }
            __syncthreads();

            const int b4 = tid & 7;
            const int i0 = tid >> 3;
            #pragma unroll
            for (int it = 0; it < 4; it++) {
                const int i  = i0 + 32 * it;
                const int c  = i >> 2;
                const int cc = i & 3;
                float4 v;
                v.x = ((const float*)&sm.tile4[4 * b4 + 0][c])[cc];
                v.y = ((const float*)&sm.tile4[4 * b4 + 1][c])[cc];
                v.z = ((const float*)&sm.tile4[4 * b4 + 2][c])[cc];
                v.w = ((const float*)&sm.tile4[4 * b4 + 3][c])[cc];
                *(float4*)&g_xt[(size_t)(in0 + i) * B_DIM + b0 + 4 * b4] = v;
            }
            __syncthreads();
            if (tid == 0) {                          // release this tile
                __threadfence();
                atomicAdd(&g_tdone[q], 1);
            }
        } else {
            // ================= gather task =================
            const int o0 = j * OTILE;

            // Stage indices / weights / bias
            if (tid < 64) {
                sm.g.sidx4[tid >> 3][tid & 7] =
                    ((const int4*)idx)[(size_t)(o0 + (tid >> 3)) * 8 + (tid & 7)];
            } else if (tid < 128) {
                const int u = tid - 64;
                sm.g.sw4[u >> 3][u & 7] =
                    ((const float4*)w)[(size_t)(o0 + (u >> 3)) * 8 + (u & 7)];
            } else if (tid < 128 + OTILE) {
                sm.g.sbias[tid - 128] = bias[o0 + (tid - 128)];
            }

            // Wait for this quarter's transpose (acquire)
            if (tid == 0) {
                while (*(volatile int*)&g_tdone[q] < TT) __nanosleep(64);
                __threadfence();
            }
            __syncthreads();

            // Warp w handles output o0+w; lanes = 32 b-quads of the quarter.
            const int q32 = tid & 31;
            const int oo  = tid >> 5;
            const float4* __restrict__ xt4 =
                reinterpret_cast<const float4*>(g_xt) + q * 32 + q32;

            float4 acc = make_float4(0.f, 0.f, 0.f, 0.f);
            #pragma unroll
            for (int k4 = 0; k4 < K_DIM / 4; k4++) {
                const int4   ii = sm.g.sidx4[oo][k4];
                const float4 ww = sm.g.sw4[oo][k4];
                const float4 v0 = __ldg(&xt4[(size_t)ii.x * (B_DIM / 4)]);
                const float4 v1 = __ldg(&xt4[(size_t)ii.y * (B_DIM / 4)]);
                const float4 v2 = __ldg(&xt4[(size_t)ii.z * (B_DIM / 4)]);
                const float4 v3 = __ldg(&xt4[(size_t)ii.w * (B_DIM / 4)]);
                acc.x += v0.x * ww.x; acc.y += v0.y * ww.x;
                acc.z += v0.z * ww.x; acc.w += v0.w * ww.x;
                acc.x += v1.x * ww.y; acc.y += v1.y * ww.y;
                acc.z += v1.z * ww.y; acc.w += v1.w * ww.y;
                acc.x += v2.x * ww.z; acc.y += v2.y * ww.z;
                acc.z += v2.z * ww.z; acc.w += v2.w * ww.z;
                acc.x += v3.x * ww.w; acc.y += v3.y * ww.w;
                acc.z += v3.z * ww.w; acc.w += v3.w * ww.w;
            }
            const float bv = sm.g.sbias[oo];
            acc.x += bv; acc.y += bv; acc.z += bv; acc.w += bv;
            // Conflict-free STS.128: warp writes a contiguous 512B row
            *(float4*)&sm.g.sout2[oo][4 * q32] = acc;
            __syncthreads();

            // Coalesced out store: thread tid<128 owns b = q*128+tid,
            // writes out[b][o0..o0+7] as two STG.128.
            if (tid < QB) {
                const int b = q * QB + tid;
                float4 r0, r1;
                r0.x = sm.g.sout2[0][tid]; r0.y = sm.g.sout2[1][tid];
                r0.z = sm.g.sout2[2][tid]; r0.w = sm.g.sout2[3][tid];
                r1.x = sm.g.sout2[4][tid]; r1.y = sm.g.sout2[5][tid];
                r1.z = sm.g.sout2[6][tid]; r1.w = sm.g.sout2[7][tid];
                float4* dst = reinterpret_cast<float4*>(
                    out + (size_t)b * OUT_DIM + o0);
                dst[0] = r0;
                dst[1] = r1;
            }
        }
    }
}

// ---------------------------------------------------------------------------
// Launch
// ---------------------------------------------------------------------------
extern "C" void kernel_launch(void* const* d_in, const int* in_sizes, int n_in,
                              void* d_out, int out_size) {
    const float* x    = (const float*)d_in[0];
    const int*   idx  = (const int*)  d_in[1];
    const float* w    = (const float*)d_in[2];
    const float* bias = (const float*)d_in[3];
    float*       out  = (float*)d_out;

    reset_kernel<<<1, 1>>>();
    persistent_kernel<<<888, 256>>>(x, idx, w, bias, out);
}

// round 6
// speedup vs baseline: 1.4151x; 1.4151x over previous
#include <cuda_runtime.h>
#include <cuda_fp16.h>
#include <cstdint>

// Problem constants
#define B_DIM   512
#define HALF_B  256
#define IN_DIM  65536
#define OUT_DIM 16384
#define K_DIM   32
#define OTILE   8

// 64 MB scratch for transposed x in fp16: xt[in][b]
__device__ __half g_xt_h[(size_t)IN_DIM * B_DIM];

// Bit-reinterpretation helpers (the named intrinsics don't exist here)
__device__ __forceinline__ unsigned int h2_to_u32(__half2 h) {
    union { __half2 h; unsigned int u; } c; c.h = h; return c.u;
}
__device__ __forceinline__ float2 u32_to_f2(unsigned int u) {
    union { unsigned int u; __half2 h; } c; c.u = u;
    return __half22float2(c.h);
}

// ---------------------------------------------------------------------------
// Kernel 1: transpose + fp16-convert one b-half of x into xt.
// Tile: 32 b-rows x 128 in-cols. Block 256 threads.
// ---------------------------------------------------------------------------
__global__ __launch_bounds__(256) void transpose_half_kernel(
    const float* __restrict__ x, int half)
{
    __shared__ float4 tile4[32][33];           // [b_row][in_col/4], padded

    const int in0 = blockIdx.x * 128;
    const int b0  = half * HALF_B + blockIdx.y * 32;
    const int t   = threadIdx.x;

    // Load: float4 along IN. Warp reads 128B-contiguous per row.
    const int c4 = t & 31;
    const int r0 = t >> 5;
    #pragma unroll
    for (int it = 0; it < 4; it++) {
        const int r = r0 + 8 * it;
        tile4[r][c4] =
            *(const float4*)&x[(size_t)(b0 + r) * IN_DIM + in0 + 4 * c4];
    }
    __syncthreads();

    // Store: thread t owns in-row i = t>>1, b-chunk p = t&1 (16 b's = 32B).
    const int i = t >> 1;                      // 0..127
    const int p = t & 1;
    const int c  = i >> 2;                     // tile4 column
    const int cc = i & 3;                      // component within float4

    __half2 h2[8];
    #pragma unroll
    for (int j = 0; j < 8; j++) {
        const float f0 = ((const float*)&tile4[16 * p + 2 * j + 0][c])[cc];
        const float f1 = ((const float*)&tile4[16 * p + 2 * j + 1][c])[cc];
        h2[j] = __floats2half2_rn(f0, f1);
    }
    uint4 u0, u1;
    u0.x = h2_to_u32(h2[0]); u0.y = h2_to_u32(h2[1]);
    u0.z = h2_to_u32(h2[2]); u0.w = h2_to_u32(h2[3]);
    u1.x = h2_to_u32(h2[4]); u1.y = h2_to_u32(h2[5]);
    u1.z = h2_to_u32(h2[6]); u1.w = h2_to_u32(h2[7]);

    uint4* dst = (uint4*)&g_xt_h[(size_t)(in0 + i) * B_DIM + b0 + 16 * p];
    dst[0] = u0;
    dst[1] = u1;
}

// ---------------------------------------------------------------------------
// Kernel 2: gather + dot for one b-half (xt half = 32MB fp16, L2-hot from the
// preceding transpose). Block = 8 warps = 8 outputs; lane owns 8 b-rows.
// Each (o,k) column read is a contiguous 512B block (32 lanes x LDG.128).
// ---------------------------------------------------------------------------
__global__ __launch_bounds__(256) void sparse_linear_kernel(
    const int*   __restrict__ idx,
    const float* __restrict__ w,
    const float* __restrict__ bias,
    float*       __restrict__ out,
    int half)
{
    const int o0  = blockIdx.x * OTILE;
    const int tid = threadIdx.x;
    const int wo  = tid >> 5;                  // warp -> output o0+wo
    const int l   = tid & 31;                  // lane -> b = half*256 + 8l..8l+7

    __shared__ int4   sidx4[OTILE][K_DIM / 4];
    __shared__ float4 sw4[OTILE][K_DIM / 4];
    __shared__ float  sbias[OTILE];
    __shared__ float  sout[OTILE][HALF_B + 8]; // [o][b], small pad

    // Stage indices / weights / bias
    if (tid < 64) {
        sidx4[tid >> 3][tid & 7] =
            ((const int4*)idx)[(size_t)(o0 + (tid >> 3)) * 8 + (tid & 7)];
    } else if (tid < 128) {
        const int u = tid - 64;
        sw4[u >> 3][u & 7] =
            ((const float4*)w)[(size_t)(o0 + (u >> 3)) * 8 + (u & 7)];
    } else if (tid < 128 + OTILE) {
        sbias[tid - 128] = bias[o0 + (tid - 128)];
    }
    __syncthreads();

    // xt row = 512 halfs = 64 uint4. Lane l covers uint4 slot (half*32 + l).
    const uint4* __restrict__ xt16 =
        reinterpret_cast<const uint4*>(g_xt_h) + (size_t)half * 32 + l;

    float a0 = 0.f, a1 = 0.f, a2 = 0.f, a3 = 0.f;
    float a4 = 0.f, a5 = 0.f, a6 = 0.f, a7 = 0.f;

    #pragma unroll
    for (int k4 = 0; k4 < K_DIM / 4; k4++) {
        const int4   ii = sidx4[wo][k4];       // LDS.128 broadcast
        const float4 ww = sw4[wo][k4];         // LDS.128 broadcast
        const uint4 v0 = __ldg(&xt16[(size_t)ii.x * 64]);
        const uint4 v1 = __ldg(&xt16[(size_t)ii.y * 64]);
        const uint4 v2 = __ldg(&xt16[(size_t)ii.z * 64]);
        const uint4 v3 = __ldg(&xt16[(size_t)ii.w * 64]);

        {
            const float2 f0 = u32_to_f2(v0.x);
            const float2 f1 = u32_to_f2(v0.y);
            const float2 f2 = u32_to_f2(v0.z);
            const float2 f3 = u32_to_f2(v0.w);
            a0 += f0.x * ww.x; a1 += f0.y * ww.x;
            a2 += f1.x * ww.x; a3 += f1.y * ww.x;
            a4 += f2.x * ww.x; a5 += f2.y * ww.x;
            a6 += f3.x * ww.x; a7 += f3.y * ww.x;
        }
        {
            const float2 f0 = u32_to_f2(v1.x);
            const float2 f1 = u32_to_f2(v1.y);
            const float2 f2 = u32_to_f2(v1.z);
            const float2 f3 = u32_to_f2(v1.w);
            a0 += f0.x * ww.y; a1 += f0.y * ww.y;
            a2 += f1.x * ww.y; a3 += f1.y * ww.y;
            a4 += f2.x * ww.y; a5 += f2.y * ww.y;
            a6 += f3.x * ww.y; a7 += f3.y * ww.y;
        }
        {
            const float2 f0 = u32_to_f2(v2.x);
            const float2 f1 = u32_to_f2(v2.y);
            const float2 f2 = u32_to_f2(v2.z);
            const float2 f3 = u32_to_f2(v2.w);
            a0 += f0.x * ww.z; a1 += f0.y * ww.z;
            a2 += f1.x * ww.z; a3 += f1.y * ww.z;
            a4 += f2.x * ww.z; a5 += f2.y * ww.z;
            a6 += f3.x * ww.z; a7 += f3.y * ww.z;
        }
        {
            const float2 f0 = u32_to_f2(v3.x);
            const float2 f1 = u32_to_f2(v3.y);
            const float2 f2 = u32_to_f2(v3.z);
            const float2 f3 = u32_to_f2(v3.w);
            a0 += f0.x * ww.w; a1 += f0.y * ww.w;
            a2 += f1.x * ww.w; a3 += f1.y * ww.w;
            a4 += f2.x * ww.w; a5 += f2.y * ww.w;
            a6 += f3.x * ww.w; a7 += f3.y * ww.w;
        }
    }

    const float bv = sbias[wo];
    float4 s0 = make_float4(a0 + bv, a1 + bv, a2 + bv, a3 + bv);
    float4 s1 = make_float4(a4 + bv, a5 + bv, a6 + bv, a7 + bv);
    *(float4*)&sout[wo][8 * l + 0] = s0;
    *(float4*)&sout[wo][8 * l + 4] = s1;
    __syncthreads();

    // Coalesced out store: thread t owns b = half*256 + t, writes
    // out[b][o0..o0+7] as two STG.128 (each 32B sector written whole).
    {
        const int b = half * HALF_B + tid;
        float4 r0, r1;
        r0.x = sout[0][tid]; r0.y = sout[1][tid];
        r0.z = sout[2][tid]; r0.w = sout[3][tid];
        r1.x = sout[4][tid]; r1.y = sout[5][tid];
        r1.z = sout[6][tid]; r1.w = sout[7][tid];
        float4* dst = reinterpret_cast<float4*>(out + (size_t)b * OUT_DIM + o0);
        dst[0] = r0;
        dst[1] = r1;
    }
}

// ---------------------------------------------------------------------------
// Launch: serial halves (overlap cannot help — LTS cap is shared; see R4).
// ---------------------------------------------------------------------------
extern "C" void kernel_launch(void* const* d_in, const int* in_sizes, int n_in,
                              void* d_out, int out_size) {
    const float* x    = (const float*)d_in[0];
    const int*   idx  = (const int*)  d_in[1];
    const float* w    = (const float*)d_in[2];
    const float* bias = (const float*)d_in[3];
    float*       out  = (float*)d_out;

    dim3 tb(256);
    dim3 tg(IN_DIM / 128, HALF_B / 32);        // (512, 8) per half
    dim3 gg(OUT_DIM / OTILE);                  // 2048 per half

    transpose_half_kernel<<<tg, tb>>>(x, 0);
    sparse_linear_kernel<<<gg, 256>>>(idx, w, bias, out, 0);
    transpose_half_kernel<<<tg, tb>>>(x, 1);
    sparse_linear_kernel<<<gg, 256>>>(idx, w, bias, out, 1);
}

// round 7
// speedup vs baseline: 1.5303x; 1.0814x over previous
#include <cuda_runtime.h>
#include <cuda_fp16.h>
#include <cstdint>

// Problem constants
#define B_DIM   512
#define HALF_B  256
#define IN_DIM  65536
#define OUT_DIM 16384
#define K_DIM   32
#define OTILE   8

// 64 MB scratch for transposed x in fp16: xt[in][b]
__device__ __half g_xt_h[(size_t)IN_DIM * B_DIM];

// Bit-reinterpretation helpers
__device__ __forceinline__ unsigned int h2_to_u32(__half2 h) {
    union { __half2 h; unsigned int u; } c; c.h = h; return c.u;
}
__device__ __forceinline__ float2 u32_to_f2(unsigned int u) {
    union { unsigned int u; __half2 h; } c; c.u = u;
    return __half22float2(c.h);
}

// Shared-memory shapes (union -> fused kernel footprint = max, not sum)
struct SmemT {
    float4 tile4[32][33];                      // 16.9 KB
};
struct SmemG {
    int4   sidx4[OTILE][K_DIM / 4];
    float4 sw4[OTILE][K_DIM / 4];
    float  sbias[OTILE];
    float  sout[OTILE][HALF_B + 8];            // ~10.5 KB total
};
union SmemU { SmemT t; SmemG g; };

// ---------------------------------------------------------------------------
// Transpose tile body: 32 b-rows x 128 in-cols of x -> fp16 xt.
// ---------------------------------------------------------------------------
__device__ __forceinline__ void transpose_tile(
    const float* __restrict__ x, int in0, int b0, SmemT& s)
{
    const int t = threadIdx.x;

    const int c4 = t & 31;
    const int r0 = t >> 5;
    #pragma unroll
    for (int it = 0; it < 4; it++) {
        const int r = r0 + 8 * it;
        s.tile4[r][c4] =
            *(const float4*)&x[(size_t)(b0 + r) * IN_DIM + in0 + 4 * c4];
    }
    __syncthreads();

    const int i = t >> 1;                      // in-row 0..127
    const int p = t & 1;                       // b-chunk (16 b = 32B)
    const int c  = i >> 2;
    const int cc = i & 3;

    __half2 h2[8];
    #pragma unroll
    for (int j = 0; j < 8; j++) {
        const float f0 = ((const float*)&s.tile4[16 * p + 2 * j + 0][c])[cc];
        const float f1 = ((const float*)&s.tile4[16 * p + 2 * j + 1][c])[cc];
        h2[j] = __floats2half2_rn(f0, f1);
    }
    uint4 u0, u1;
    u0.x = h2_to_u32(h2[0]); u0.y = h2_to_u32(h2[1]);
    u0.z = h2_to_u32(h2[2]); u0.w = h2_to_u32(h2[3]);
    u1.x = h2_to_u32(h2[4]); u1.y = h2_to_u32(h2[5]);
    u1.z = h2_to_u32(h2[6]); u1.w = h2_to_u32(h2[7]);

    uint4* dst = (uint4*)&g_xt_h[(size_t)(in0 + i) * B_DIM + b0 + 16 * p];
    dst[0] = u0;
    dst[1] = u1;
}

// ---------------------------------------------------------------------------
// Gather block body: 8 outputs x one b-half. Warp per output; lane owns
// 8 b-rows via one LDG.128 per (o,k) -> 512B contiguous column reads.
// ---------------------------------------------------------------------------
__device__ __forceinline__ void gather_block(
    const int*   __restrict__ idx,
    const float* __restrict__ w,
    const float* __restrict__ bias,
    float*       __restrict__ out,
    int half, int o0, SmemG& s)
{
    const int tid = threadIdx.x;
    const int wo  = tid >> 5;
    const int l   = tid & 31;

    if (tid < 64) {
        s.sidx4[tid >> 3][tid & 7] =
            ((const int4*)idx)[(size_t)(o0 + (tid >> 3)) * 8 + (tid & 7)];
    } else if (tid < 128) {
        const int u = tid - 64;
        s.sw4[u >> 3][u & 7] =
            ((const float4*)w)[(size_t)(o0 + (u >> 3)) * 8 + (u & 7)];
    } else if (tid < 128 + OTILE) {
        s.sbias[tid - 128] = bias[o0 + (tid - 128)];
    }
    __syncthreads();

    const uint4* __restrict__ xt16 =
        reinterpret_cast<const uint4*>(g_xt_h) + (size_t)half * 32 + l;

    float a0 = 0.f, a1 = 0.f, a2 = 0.f, a3 = 0.f;
    float a4 = 0.f, a5 = 0.f, a6 = 0.f, a7 = 0.f;

    #pragma unroll
    for (int k4 = 0; k4 < K_DIM / 4; k4++) {
        const int4   ii = s.sidx4[wo][k4];
        const float4 ww = s.sw4[wo][k4];
        const uint4 v0 = __ldg(&xt16[(size_t)ii.x * 64]);
        const uint4 v1 = __ldg(&xt16[(size_t)ii.y * 64]);
        const uint4 v2 = __ldg(&xt16[(size_t)ii.z * 64]);
        const uint4 v3 = __ldg(&xt16[(size_t)ii.w * 64]);

        {
            const float2 f0 = u32_to_f2(v0.x), f1 = u32_to_f2(v0.y);
            const float2 f2 = u32_to_f2(v0.z), f3 = u32_to_f2(v0.w);
            a0 += f0.x * ww.x; a1 += f0.y * ww.x;
            a2 += f1.x * ww.x; a3 += f1.y * ww.x;
            a4 += f2.x * ww.x; a5 += f2.y * ww.x;
            a6 += f3.x * ww.x; a7 += f3.y * ww.x;
        }
        {
            const float2 f0 = u32_to_f2(v1.x), f1 = u32_to_f2(v1.y);
            const float2 f2 = u32_to_f2(v1.z), f3 = u32_to_f2(v1.w);
            a0 += f0.x * ww.y; a1 += f0.y * ww.y;
            a2 += f1.x * ww.y; a3 += f1.y * ww.y;
            a4 += f2.x * ww.y; a5 += f2.y * ww.y;
            a6 += f3.x * ww.y; a7 += f3.y * ww.y;
        }
        {
            const float2 f0 = u32_to_f2(v2.x), f1 = u32_to_f2(v2.y);
            const float2 f2 = u32_to_f2(v2.z), f3 = u32_to_f2(v2.w);
            a0 += f0.x * ww.z; a1 += f0.y * ww.z;
            a2 += f1.x * ww.z; a3 += f1.y * ww.z;
            a4 += f2.x * ww.z; a5 += f2.y * ww.z;
            a6 += f3.x * ww.z; a7 += f3.y * ww.z;
        }
        {
            const float2 f0 = u32_to_f2(v3.x), f1 = u32_to_f2(v3.y);
            const float2 f2 = u32_to_f2(v3.z), f3 = u32_to_f2(v3.w);
            a0 += f0.x * ww.w; a1 += f0.y * ww.w;
            a2 += f1.x * ww.w; a3 += f1.y * ww.w;
            a4 += f2.x * ww.w; a5 += f2.y * ww.w;
            a6 += f3.x * ww.w; a7 += f3.y * ww.w;
        }
    }

    const float bv = s.sbias[wo];
    float4 s0 = make_float4(a0 + bv, a1 + bv, a2 + bv, a3 + bv);
    float4 s1 = make_float4(a4 + bv, a5 + bv, a6 + bv, a7 + bv);
    *(float4*)&s.sout[wo][8 * l + 0] = s0;
    *(float4*)&s.sout[wo][8 * l + 4] = s1;
    __syncthreads();

    {
        const int b = half * HALF_B + tid;
        float4 r0, r1;
        r0.x = s.sout[0][tid]; r0.y = s.sout[1][tid];
        r0.z = s.sout[2][tid]; r0.w = s.sout[3][tid];
        r1.x = s.sout[4][tid]; r1.y = s.sout[5][tid];
        r1.z = s.sout[6][tid]; r1.w = s.sout[7][tid];
        float4* dst = reinterpret_cast<float4*>(out + (size_t)b * OUT_DIM + o0);
        dst[0] = r0;
        dst[1] = r1;
    }
}

// ---------------------------------------------------------------------------
// Kernels
// ---------------------------------------------------------------------------
__global__ __launch_bounds__(256) void transpose_half_kernel(
    const float* __restrict__ x, int half)
{
    __shared__ SmemT s;
    const int j   = blockIdx.x;                // 0..4095
    const int in0 = (j & 511) << 7;
    const int b0  = half * HALF_B + (j >> 9) * 32;
    transpose_tile(x, in0, b0, s);
}

__global__ __launch_bounds__(256) void sparse_linear_kernel(
    const int*   __restrict__ idx,
    const float* __restrict__ w,
    const float* __restrict__ bias,
    float*       __restrict__ out,
    int half)
{
    __shared__ SmemG s;
    gather_block(idx, w, bias, out, half, blockIdx.x * OTILE, s);
}

// Fused: gather(half 0) and transpose(half 1) are independent (disjoint xt
// regions) -> run them concurrently in one launch, partitioned by blockIdx.
__global__ __launch_bounds__(256) void fused_g0_t1_kernel(
    const float* __restrict__ x,
    const int*   __restrict__ idx,
    const float* __restrict__ w,
    const float* __restrict__ bias,
    float*       __restrict__ out)
{
    __shared__ SmemU sm;
    const int bx = blockIdx.x;
    if (bx < OUT_DIM / OTILE) {
        gather_block(idx, w, bias, out, 0, bx * OTILE, sm.g);
    } else {
        const int j   = bx - OUT_DIM / OTILE;  // 0..4095
        const int in0 = (j & 511) << 7;
        const int b0  = HALF_B + (j >> 9) * 32;
        transpose_tile(x, in0, b0, sm.t);
    }
}

// ---------------------------------------------------------------------------
// Launch: T(h0) ; [G(h0) || T(h1)] ; G(h1)
// ---------------------------------------------------------------------------
extern "C" void kernel_launch(void* const* d_in, const int* in_sizes, int n_in,
                              void* d_out, int out_size) {
    const float* x    = (const float*)d_in[0];
    const int*   idx  = (const int*)  d_in[1];
    const float* w    = (const float*)d_in[2];
    const float* bias = (const float*)d_in[3];
    float*       out  = (float*)d_out;

    transpose_half_kernel<<<4096, 256>>>(x, 0);
    fused_g0_t1_kernel<<<2048 + 4096, 256>>>(x, idx, w, bias, out);
    sparse_linear_kernel<<<2048, 256>>>(idx, w, bias, out, 1);
}